// round 9
// baseline (speedup 1.0000x reference)
#include <cuda_runtime.h>
#include <math.h>

// Problem constants (B=4, S=2048, D_IN=1024, D_OUT=1024, E=8, K=2)
#define BTOK    8192
#define DIN     1024
#define DOUT    1024
#define NE      8
#define NROW    24          // 8 gate rows + 16 expert rows (e, o in {0,1})
#define SPLITK  8
#define KSPAN   (DIN / SPLITK)   // 128 k per block
#define TK      64          // k sub-chunk staged in smem
#define TM      128         // tokens per group/block (thread = token)
#define NGRP    (BTOK / TM) // 64 groups
#define TPB     128

#define XSS 68              // xs row stride: banks 4*lane -> conflict-free LDS.128
#define WSS 132             // ws row stride (16B aligned)

// Partials: scratch[(split*NROW + row)*BTOK + token]
__device__ float g_scratch[SPLITK * NROW * BTOK];   // 6.3 MB
__device__ unsigned g_cnt[NGRP];                    // zero-init; winner resets

__device__ __forceinline__ unsigned long long fma2(unsigned long long a,
                                                   unsigned long long b,
                                                   unsigned long long c) {
    unsigned long long d;
    asm("fma.rn.f32x2 %0, %1, %2, %3;" : "=l"(d) : "l"(a), "l"(b), "l"(c));
    return d;
}
__device__ __forceinline__ void unpack2(unsigned long long v, float& lo, float& hi) {
    asm("mov.b64 {%0, %1}, %2;" : "=f"(lo), "=f"(hi) : "l"(v));
}

// ---------------------------------------------------------------------------
// Fused kernel: split-K GEMM partials; last block per group does
// reduce + gating + broadcast output write (threadfence-reduction pattern).
// ---------------------------------------------------------------------------
__global__ __launch_bounds__(TPB)
void moe_fused_kernel(const float* __restrict__ x,
                      const float* __restrict__ gate_w,
                      const float* __restrict__ gate_b,
                      const float* __restrict__ ebias,
                      const float* __restrict__ expert_w,
                      const float* __restrict__ expert_b,
                      float* __restrict__ out,
                      float* __restrict__ idx_out)
{
    __shared__ float xs[TM][XSS];      // 34816 B
    __shared__ float ws[NROW][WSS];    // 12672 B
    __shared__ float wtok[TM];
    __shared__ unsigned s_last;

    const int tid   = threadIdx.x;
    const int split = blockIdx.x & (SPLITK - 1);
    const int grp   = blockIdx.x >> 3;
    const int tok0  = grp * TM;
    const int token = tok0 + tid;
    const int kbase = split * KSPAN;

    // ---- load weight tile once: 24 rows x 128 floats = 768 float4 ----
    #pragma unroll
    for (int j = 0; j < (NROW * KSPAN) / (4 * TPB); j++) {   // 6
        int i   = tid + j * TPB;
        int row = i >> 5;
        int f4  = (i & 31) << 2;
        const float* src = (row < NE)
            ? (gate_w + (size_t)row * DIN)
            : (expert_w + ((size_t)(((row - NE) >> 1) * DOUT + ((row - NE) & 1))) * DIN);
        float4 v = *(const float4*)(src + kbase + f4);
        *(float4*)&ws[row][f4] = v;
    }

    unsigned long long acc[NROW];
    #pragma unroll
    for (int r = 0; r < NROW; r++) acc[r] = 0ULL;

    #pragma unroll
    for (int c = 0; c < KSPAN / TK; c++) {            // 2 chunks
        const int k0 = kbase + c * TK;
        if (c > 0) __syncthreads();                   // xs reuse guard

        // ---- stage x chunk: 128 tok x 64 floats = 2048 float4, coalesced ----
        #pragma unroll
        for (int j = 0; j < (TM * TK) / (4 * TPB); j++) {    // 16
            int i  = tid + j * TPB;
            int m  = i >> 4;
            int f4 = (i & 15) << 2;
            float4 v = *(const float4*)(x + (size_t)(tok0 + m) * DIN + k0 + f4);
            *(float4*)&xs[m][f4] = v;
        }
        __syncthreads();

        // ---- compute: thread = token, all 24 rows, FFMA2 over k-pairs ----
        const float* xr = &xs[tid][0];
        #pragma unroll 4
        for (int q = 0; q < TK; q += 4) {
            ulonglong2 xv = *(const ulonglong2*)(xr + q);
            const int kk = c * TK + q;
            #pragma unroll
            for (int r = 0; r < NROW; r++) {
                ulonglong2 wv = *(const ulonglong2*)(&ws[r][kk]);  // broadcast
                acc[r] = fma2(xv.x, wv.x, acc[r]);
                acc[r] = fma2(xv.y, wv.y, acc[r]);
            }
        }
    }

    // ---- write partials, coalesced: [split][row][token] ----
    #pragma unroll
    for (int r = 0; r < NROW; r++) {
        float lo, hi;
        unpack2(acc[r], lo, hi);
        g_scratch[((size_t)(split * NROW + r)) * BTOK + token] = lo + hi;
    }

    // ---- last-block election (threadFenceReduction pattern) ----
    __threadfence();
    __syncthreads();
    if (tid == 0) {
        unsigned old = atomicAdd(&g_cnt[grp], 1u);
        s_last = (old == SPLITK - 1);
        if (s_last) g_cnt[grp] = 0;        // reset for next graph replay
    }
    __syncthreads();
    if (!s_last) return;

    // =============== winner: reduce + gate + broadcast write ===============
    {
        float P[NROW];
        #pragma unroll
        for (int r = 0; r < NROW; r++) P[r] = 0.f;
        #pragma unroll
        for (int sp = 0; sp < SPLITK; sp++)
            #pragma unroll
            for (int r = 0; r < NROW; r++)
                P[r] += g_scratch[((size_t)(sp * NROW + r)) * BTOK + token];

        float l[NE];
        #pragma unroll
        for (int e = 0; e < NE; e++)
            l[e] = P[e] + gate_b[e] + ebias[e];

        int e0 = 0; float b0 = l[0];
        #pragma unroll
        for (int e = 1; e < NE; e++)
            if (l[e] > b0) { b0 = l[e]; e0 = e; }
        int e1 = -1; float b1 = -INFINITY;
        #pragma unroll
        for (int e = 0; e < NE; e++) {
            if (e == e0) continue;
            if (l[e] > b1) { b1 = l[e]; e1 = e; }
        }

        float p0 = 1.f / (1.f + expf(-b0));
        float p1 = 1.f / (1.f + expf(-b1));
        float inv = 1.f / (p0 + p1);

        float v0 = P[NE + e0 * 2 + 0] + expert_b[(size_t)e0 * DOUT + 0];
        float v1 = P[NE + e1 * 2 + 1] + expert_b[(size_t)e1 * DOUT + 1];
        wtok[tid] = (v0 * p0 + v1 * p1) * inv;

        if (idx_out) {
            idx_out[(size_t)token * 2 + 0] = (float)e0;
            idx_out[(size_t)token * 2 + 1] = (float)e1;
        }
    }
    __syncthreads();

    // ---- broadcast write: 128 threads x 2 float4-passes per token ----
    const int fo = tid << 2;
    #pragma unroll 4
    for (int m = 0; m < TM; m++) {
        float v = wtok[m];
        float4 v4 = make_float4(v, v, v, v);
        float* base = out + (size_t)(tok0 + m) * DOUT;
        *(float4*)(base + fo) = v4;
        *(float4*)(base + 512 + fo) = v4;
    }
}

extern "C" void kernel_launch(void* const* d_in, const int* in_sizes, int n_in,
                              void* d_out, int out_size)
{
    const float* x        = (const float*)d_in[0];
    const float* gate_w   = (const float*)d_in[1];
    const float* gate_b   = (const float*)d_in[2];
    const float* ebias    = (const float*)d_in[3];
    const float* expert_w = (const float*)d_in[4];
    const float* expert_b = (const float*)d_in[5];
    float* out = (float*)d_out;

    float* idx_out = nullptr;
    long long base = (long long)BTOK * DOUT;
    if ((long long)out_size >= base + (long long)BTOK * 2)
        idx_out = out + base;

    moe_fused_kernel<<<NGRP * SPLITK, TPB>>>(x, gate_w, gate_b, ebias,
                                             expert_w, expert_b, out, idx_out);
}

// round 10
// speedup vs baseline: 1.3456x; 1.3456x over previous
#include <cuda_runtime.h>
#include <math.h>

// Problem constants (B=4, S=2048, D_IN=1024, D_OUT=1024, E=8, K=2)
#define BTOK    8192
#define DIN     1024
#define DOUT    1024
#define NE      8
#define NROW    24          // 8 gate rows + 16 expert rows (e, o in {0,1})
#define SPLITK  8
#define KSPAN   (DIN / SPLITK)   // 128 k per block
#define CH      16          // k per pipelined chunk
#define NCH     (KSPAN / CH)     // 8
#define TM      128         // tokens per block (thread = token)
#define TPB     128
#define CHPAD   20          // xs chunk row stride (floats): conflict-free phases
#define WSS     132         // ws row stride

// Partials: scratch[(split*NROW + row)*BTOK + token]
__device__ float g_scratch[SPLITK * NROW * BTOK];   // 6.3 MB
__device__ float g_wtok[BTOK];

__device__ __forceinline__ unsigned long long fma2(unsigned long long a,
                                                   unsigned long long b,
                                                   unsigned long long c) {
    unsigned long long d;
    asm("fma.rn.f32x2 %0, %1, %2, %3;" : "=l"(d) : "l"(a), "l"(b), "l"(c));
    return d;
}
__device__ __forceinline__ void unpack2(unsigned long long v, float& lo, float& hi) {
    asm("mov.b64 {%0, %1}, %2;" : "=f"(lo), "=f"(hi) : "l"(v));
}
#define CP_ASYNC16(dst_u32, src_ptr) \
    asm volatile("cp.async.cg.shared.global [%0], [%1], 16;" \
                 :: "r"(dst_u32), "l"(src_ptr))
#define CP_COMMIT() asm volatile("cp.async.commit_group;" ::: "memory")
#define CP_WAIT(n)  asm volatile("cp.async.wait_group %0;" :: "n"(n) : "memory")

// ---------------------------------------------------------------------------
// Kernel 1: split-K skinny GEMM, cp.async double-buffered x, broadcast w.
// ---------------------------------------------------------------------------
__global__ __launch_bounds__(TPB)
void moe_gemm_kernel(const float* __restrict__ x,
                     const float* __restrict__ gate_w,
                     const float* __restrict__ expert_w)
{
    __shared__ float xs[2][TM][CHPAD];   // 20480 B
    __shared__ float ws[NROW][WSS];      // 12672 B

    const int tid   = threadIdx.x;
    const int split = blockIdx.x & (SPLITK - 1);
    const int grp   = blockIdx.x >> 3;
    const int tok0  = grp * TM;
    const int token = tok0 + tid;
    const int kbase = split * KSPAN;

    // ---- issue chunk 0 (cp.async) ----
    #pragma unroll
    for (int j = 0; j < 4; j++) {
        int i = tid + j * TPB;
        int m = i >> 2;
        int f = (i & 3) << 2;
        unsigned dst = (unsigned)__cvta_generic_to_shared(&xs[0][m][f]);
        CP_ASYNC16(dst, x + (size_t)(tok0 + m) * DIN + kbase + f);
    }
    CP_COMMIT();

    // ---- load weight tile: 24 rows x 128 floats = 768 float4 ----
    #pragma unroll
    for (int j = 0; j < (NROW * KSPAN) / (4 * TPB); j++) {   // 6
        int i   = tid + j * TPB;
        int row = i >> 5;
        int f4  = (i & 31) << 2;
        const float* src = (row < NE)
            ? (gate_w + (size_t)row * DIN)
            : (expert_w + ((size_t)(((row - NE) >> 1) * DOUT + ((row - NE) & 1))) * DIN);
        float4 v = *(const float4*)(src + kbase + f4);
        *(float4*)&ws[row][f4] = v;
    }

    unsigned long long acc[NROW];
    #pragma unroll
    for (int r = 0; r < NROW; r++) acc[r] = 0ULL;

    #pragma unroll
    for (int c = 0; c < NCH; c++) {
        const int buf = c & 1;
        if (c + 1 < NCH) {
            // issue next chunk into other buffer
            const int nk = kbase + (c + 1) * CH;
            #pragma unroll
            for (int j = 0; j < 4; j++) {
                int i = tid + j * TPB;
                int m = i >> 2;
                int f = (i & 3) << 2;
                unsigned dst = (unsigned)__cvta_generic_to_shared(&xs[buf ^ 1][m][f]);
                CP_ASYNC16(dst, x + (size_t)(tok0 + m) * DIN + nk + f);
            }
            CP_COMMIT();
            CP_WAIT(1);          // chunk c complete, c+1 may be in flight
        } else {
            CP_WAIT(0);
        }
        __syncthreads();

        // ---- compute chunk c: 16 k = 4 quads, FFMA2 ----
        const float* xr = &xs[buf][tid][0];
        #pragma unroll
        for (int q = 0; q < 4; q++) {
            ulonglong2 xv = *(const ulonglong2*)(xr + q * 4);
            const int kk = c * CH + q * 4;
            #pragma unroll
            for (int r = 0; r < NROW; r++) {
                ulonglong2 wv = *(const ulonglong2*)(&ws[r][kk]);  // broadcast
                acc[r] = fma2(xv.x, wv.x, acc[r]);
                acc[r] = fma2(xv.y, wv.y, acc[r]);
            }
        }
        __syncthreads();   // protect buf reuse by next issue
    }

    // ---- write partials, coalesced: [split][row][token] ----
    #pragma unroll
    for (int r = 0; r < NROW; r++) {
        float lo, hi;
        unpack2(acc[r], lo, hi);
        g_scratch[((size_t)(split * NROW + r)) * BTOK + token] = lo + hi;
    }
}

// ---------------------------------------------------------------------------
// Kernel 2: gating — thread = token, reduce 8 splits, top-2, write wtok + idx
// ---------------------------------------------------------------------------
__global__ __launch_bounds__(256)
void moe_gate_kernel(const float* __restrict__ gate_b,
                     const float* __restrict__ ebias,
                     const float* __restrict__ expert_b,
                     float* __restrict__ idx_out)
{
    const int token = blockIdx.x * 256 + threadIdx.x;

    float P[NROW];
    #pragma unroll
    for (int r = 0; r < NROW; r++) P[r] = 0.f;
    #pragma unroll
    for (int sp = 0; sp < SPLITK; sp++)
        #pragma unroll
        for (int r = 0; r < NROW; r++)
            P[r] += g_scratch[((size_t)(sp * NROW + r)) * BTOK + token];

    float l[NE];
    #pragma unroll
    for (int e = 0; e < NE; e++)
        l[e] = P[e] + gate_b[e] + ebias[e];

    int e0 = 0; float b0 = l[0];
    #pragma unroll
    for (int e = 1; e < NE; e++)
        if (l[e] > b0) { b0 = l[e]; e0 = e; }
    int e1 = -1; float b1 = -INFINITY;
    #pragma unroll
    for (int e = 0; e < NE; e++) {
        if (e == e0) continue;
        if (l[e] > b1) { b1 = l[e]; e1 = e; }
    }

    float p0 = 1.f / (1.f + expf(-b0));
    float p1 = 1.f / (1.f + expf(-b1));
    float inv = 1.f / (p0 + p1);

    float v0 = P[NE + e0 * 2 + 0] + expert_b[(size_t)e0 * DOUT + 0];
    float v1 = P[NE + e1 * 2 + 1] + expert_b[(size_t)e1 * DOUT + 1];
    g_wtok[token] = (v0 * p0 + v1 * p1) * inv;

    if (idx_out) {
        idx_out[(size_t)token * 2 + 0] = (float)e0;
        idx_out[(size_t)token * 2 + 1] = (float)e1;
    }
}

// ---------------------------------------------------------------------------
// Kernel 3: writer — 8 tokens/block, 256 threads, 8 STG.128 each
// ---------------------------------------------------------------------------
#define WTOK 8

__global__ __launch_bounds__(256)
void moe_write_kernel(float* __restrict__ out)
{
    __shared__ float wv[WTOK];
    const int tid  = threadIdx.x;
    const int tok0 = blockIdx.x * WTOK;

    if (tid < WTOK) wv[tid] = g_wtok[tok0 + tid];
    __syncthreads();

    const int fo = tid << 2;      // 256 thr x 4 floats = 1024
    #pragma unroll
    for (int m = 0; m < WTOK; m++) {
        float v = wv[m];
        float4 v4 = make_float4(v, v, v, v);
        *(float4*)(out + (size_t)(tok0 + m) * DOUT + fo) = v4;
    }
}

extern "C" void kernel_launch(void* const* d_in, const int* in_sizes, int n_in,
                              void* d_out, int out_size)
{
    const float* x        = (const float*)d_in[0];
    const float* gate_w   = (const float*)d_in[1];
    const float* gate_b   = (const float*)d_in[2];
    const float* ebias    = (const float*)d_in[3];
    const float* expert_w = (const float*)d_in[4];
    const float* expert_b = (const float*)d_in[5];
    float* out = (float*)d_out;

    float* idx_out = nullptr;
    long long base = (long long)BTOK * DOUT;
    if ((long long)out_size >= base + (long long)BTOK * 2)
        idx_out = out + base;

    moe_gemm_kernel<<<(BTOK / TM) * SPLITK, TPB>>>(x, gate_w, expert_w);
    moe_gate_kernel<<<BTOK / 256, 256>>>(gate_b, ebias, expert_b, idx_out);
    moe_write_kernel<<<BTOK / WTOK, 256>>>(out);
}

// round 11
// speedup vs baseline: 1.8876x; 1.4028x over previous
#include <cuda_runtime.h>
#include <math.h>

// Problem constants (B=4, S=2048, D_IN=1024, D_OUT=1024, E=8, K=2)
#define BTOK    8192
#define DIN     1024
#define DOUT    1024
#define NE      8
#define NROW    24          // 8 gate rows + 16 expert rows (e, o in {0,1})
#define SPLITK  8
#define KSPAN   (DIN / SPLITK)   // 128 k per block
#define CH      16          // k per pipelined chunk
#define NCH     (KSPAN / CH)     // 8
#define TM      128         // tokens per block
#define TPB     128
#define XST     20          // xs token-row stride (floats): conflict-free, 16B-aligned rows? 20*4=80B
#define WSS     132         // ws row stride

// NOTE: xs row = 20 floats = 80B -> rows alternate 16B alignment; LDS.128 needs
// 16B alignment of the ADDRESS (base + token*80 + q*16). 80 % 16 = 0 -> OK.

// Partials: scratch[(split*NROW + row)*BTOK + token]
__device__ float g_scratch[SPLITK * NROW * BTOK];   // 6.3 MB

__device__ __forceinline__ unsigned long long fma2(unsigned long long a,
                                                   unsigned long long b,
                                                   unsigned long long c) {
    unsigned long long d;
    asm("fma.rn.f32x2 %0, %1, %2, %3;" : "=l"(d) : "l"(a), "l"(b), "l"(c));
    return d;
}
__device__ __forceinline__ void unpack2(unsigned long long v, float& lo, float& hi) {
    asm("mov.b64 {%0, %1}, %2;" : "=f"(lo), "=f"(hi) : "l"(v));
}
#define CP_ASYNC16(dst_u32, src_ptr) \
    asm volatile("cp.async.cg.shared.global [%0], [%1], 16;" \
                 :: "r"(dst_u32), "l"(src_ptr))
#define CP_COMMIT() asm volatile("cp.async.commit_group;" ::: "memory")
#define CP_WAIT(n)  asm volatile("cp.async.wait_group %0;" :: "n"(n) : "memory")

// ---------------------------------------------------------------------------
// Kernel 1: split-K skinny GEMM. Warp = 12 rows x 64 tokens (2 tok/thread:
// lane & lane+32). cp.async double-buffered x; broadcast w; FFMA2.
// ---------------------------------------------------------------------------
__global__ __launch_bounds__(TPB)
void moe_gemm_kernel(const float* __restrict__ x,
                     const float* __restrict__ gate_w,
                     const float* __restrict__ expert_w)
{
    __shared__ float xs[2][TM][XST];     // 20480 B
    __shared__ float ws[NROW][WSS];      // 12672 B

    const int tid   = threadIdx.x;
    const int split = blockIdx.x & (SPLITK - 1);
    const int grp   = blockIdx.x >> 3;
    const int tok0  = grp * TM;
    const int kbase = split * KSPAN;
    const int wid   = tid >> 5;
    const int lane  = tid & 31;
    const int rb    = (wid & 1) * 12;          // row base: 0 or 12
    const int tkoff = (wid >> 1) * 64 + lane;  // first token (second = +32)

    // ---- issue x chunk 0 ----
    #pragma unroll
    for (int j = 0; j < 4; j++) {
        int i = tid + j * TPB;
        int m = i >> 2;
        int f = (i & 3) << 2;
        unsigned dst = (unsigned)__cvta_generic_to_shared(&xs[0][m][f]);
        CP_ASYNC16(dst, x + (size_t)(tok0 + m) * DIN + kbase + f);
    }
    CP_COMMIT();

    // ---- load weight tile: 24 rows x 128 floats = 768 float4 ----
    #pragma unroll
    for (int j = 0; j < (NROW * KSPAN) / (4 * TPB); j++) {   // 6
        int i   = tid + j * TPB;
        int row = i >> 5;
        int f4  = (i & 31) << 2;
        const float* src = (row < NE)
            ? (gate_w + (size_t)row * DIN)
            : (expert_w + ((size_t)(((row - NE) >> 1) * DOUT + ((row - NE) & 1))) * DIN);
        float4 v = *(const float4*)(src + kbase + f4);
        *(float4*)&ws[row][f4] = v;
    }

    unsigned long long acc0[12], acc1[12];
    #pragma unroll
    for (int r = 0; r < 12; r++) { acc0[r] = 0ULL; acc1[r] = 0ULL; }

    #pragma unroll
    for (int c = 0; c < NCH; c++) {
        const int buf = c & 1;
        if (c + 1 < NCH) {
            const int nk = kbase + (c + 1) * CH;
            #pragma unroll
            for (int j = 0; j < 4; j++) {
                int i = tid + j * TPB;
                int m = i >> 2;
                int f = (i & 3) << 2;
                unsigned dst = (unsigned)__cvta_generic_to_shared(&xs[buf ^ 1][m][f]);
                CP_ASYNC16(dst, x + (size_t)(tok0 + m) * DIN + nk + f);
            }
            CP_COMMIT();
            CP_WAIT(1);
        } else {
            CP_WAIT(0);
        }
        __syncthreads();

        // ---- compute chunk: 16 k, 12 rows, 2 tokens ----
        const float* xr0 = &xs[buf][tkoff][0];
        const float* xr1 = &xs[buf][tkoff + 32][0];
        #pragma unroll
        for (int q = 0; q < 4; q++) {
            ulonglong2 xa = *(const ulonglong2*)(xr0 + q * 4);
            ulonglong2 xb = *(const ulonglong2*)(xr1 + q * 4);
            const int kk = c * CH + q * 4;
            #pragma unroll
            for (int r = 0; r < 12; r++) {
                ulonglong2 wv = *(const ulonglong2*)(&ws[rb + r][kk]);  // broadcast
                acc0[r] = fma2(xa.x, wv.x, acc0[r]);
                acc0[r] = fma2(xa.y, wv.y, acc0[r]);
                acc1[r] = fma2(xb.x, wv.x, acc1[r]);
                acc1[r] = fma2(xb.y, wv.y, acc1[r]);
            }
        }
        __syncthreads();
    }

    // ---- write partials, coalesced: [split][row][token] ----
    const int token = tok0 + tkoff;
    #pragma unroll
    for (int r = 0; r < 12; r++) {
        float lo, hi;
        float* dst = g_scratch + ((size_t)(split * NROW + rb + r)) * BTOK + token;
        unpack2(acc0[r], lo, hi);
        dst[0]  = lo + hi;
        unpack2(acc1[r], lo, hi);
        dst[32] = lo + hi;
    }
}

// ---------------------------------------------------------------------------
// Kernel 2: parallel reduce + gating epilogue + broadcast write (R5 shape)
// ---------------------------------------------------------------------------
#define ETOK 32
#define ETH  256
#define PST  25

__global__ __launch_bounds__(ETH)
void moe_epilogue_kernel(const float* __restrict__ gate_b,
                         const float* __restrict__ ebias,
                         const float* __restrict__ expert_b,
                         float* __restrict__ out,
                         float* __restrict__ idx_out)
{
    __shared__ float Pp[SPLITK][ETOK][PST];   // 25.6 KB
    __shared__ float Pfin[ETOK][PST];
    __shared__ float wtok[ETOK];

    const int tid  = threadIdx.x;
    const int tok0 = blockIdx.x * ETOK;

    // ---- Phase A: thread = (token, split); 24 coalesced loads each ----
    {
        const int token = tid & 31;
        const int slot  = tid >> 5;          // 0..7 = split
        const float* src = g_scratch + (size_t)(slot * NROW) * BTOK + tok0 + token;
        float* dst = &Pp[slot][token][0];
        #pragma unroll
        for (int r = 0; r < NROW; r++)
            dst[r] = src[(size_t)r * BTOK];
    }
    __syncthreads();

    // ---- Phase B: 768 cells (32 tok x 24 rows), 3 per thread ----
    #pragma unroll
    for (int cb = 0; cb < 3; cb++) {
        int cell  = tid * 3 + cb;
        int token = cell / NROW;
        int r     = cell - token * NROW;
        float s = 0.f;
        #pragma unroll
        for (int sp = 0; sp < SPLITK; sp++)
            s += Pp[sp][token][r];
        Pfin[token][r] = s;
    }
    __syncthreads();

    // ---- Phase C: gating (threads 0..31) ----
    if (tid < ETOK) {
        const float* Pm = &Pfin[tid][0];
        float l[NE];
        #pragma unroll
        for (int e = 0; e < NE; e++)
            l[e] = Pm[e] + gate_b[e] + ebias[e];

        int e0 = 0; float b0 = l[0];
        #pragma unroll
        for (int e = 1; e < NE; e++)
            if (l[e] > b0) { b0 = l[e]; e0 = e; }
        int e1 = -1; float b1 = -INFINITY;
        #pragma unroll
        for (int e = 0; e < NE; e++) {
            if (e == e0) continue;
            if (l[e] > b1) { b1 = l[e]; e1 = e; }
        }

        float p0 = 1.f / (1.f + expf(-b0));
        float p1 = 1.f / (1.f + expf(-b1));
        float inv = 1.f / (p0 + p1);

        float v0 = Pm[NE + e0 * 2 + 0] + expert_b[(size_t)e0 * DOUT + 0];
        float v1 = Pm[NE + e1 * 2 + 1] + expert_b[(size_t)e1 * DOUT + 1];
        wtok[tid] = (v0 * p0 + v1 * p1) * inv;

        if (idx_out) {
            idx_out[(size_t)(tok0 + tid) * 2 + 0] = (float)e0;
            idx_out[(size_t)(tok0 + tid) * 2 + 1] = (float)e1;
        }
    }
    __syncthreads();

    // ---- Phase D: broadcast write, 256 threads x float4 per token ----
    const int fo = tid << 2;
    #pragma unroll 4
    for (int m = 0; m < ETOK; m++) {
        float v = wtok[m];
        float4 v4 = make_float4(v, v, v, v);
        *(float4*)(out + (size_t)(tok0 + m) * DOUT + fo) = v4;
    }
}

extern "C" void kernel_launch(void* const* d_in, const int* in_sizes, int n_in,
                              void* d_out, int out_size)
{
    const float* x        = (const float*)d_in[0];
    const float* gate_w   = (const float*)d_in[1];
    const float* gate_b   = (const float*)d_in[2];
    const float* ebias    = (const float*)d_in[3];
    const float* expert_w = (const float*)d_in[4];
    const float* expert_b = (const float*)d_in[5];
    float* out = (float*)d_out;

    float* idx_out = nullptr;
    long long base = (long long)BTOK * DOUT;
    if ((long long)out_size >= base + (long long)BTOK * 2)
        idx_out = out + base;

    moe_gemm_kernel<<<(BTOK / TM) * SPLITK, TPB>>>(x, gate_w, expert_w);
    moe_epilogue_kernel<<<BTOK / ETOK, ETH>>>(gate_b, ebias, expert_b,
                                              out, idx_out);
}

// round 12
// speedup vs baseline: 1.9069x; 1.0102x over previous
#include <cuda_runtime.h>
#include <math.h>

// Problem constants (B=4, S=2048, D_IN=1024, D_OUT=1024, E=8, K=2)
#define BTOK    8192
#define DIN     1024
#define DOUT    1024
#define NE      8
#define NROW    24          // 8 gate rows + 16 expert rows (e, o in {0,1})
#define SPLITK  8
#define KSPAN   (DIN / SPLITK)   // 128 k per block
#define CH      16          // k per pipelined chunk
#define NCH     (KSPAN / CH)     // 8
#define TM      128         // tokens per block
#define TPB     128
#define XST     20          // xs token-row stride (floats); 80B rows, 16B-aligned
#define WSS     132         // ws row stride

// Partials: scratch[(split*NROW + row)*BTOK + token]
__device__ float g_scratch[SPLITK * NROW * BTOK];   // 6.3 MB

__device__ __forceinline__ unsigned long long fma2(unsigned long long a,
                                                   unsigned long long b,
                                                   unsigned long long c) {
    unsigned long long d;
    asm("fma.rn.f32x2 %0, %1, %2, %3;" : "=l"(d) : "l"(a), "l"(b), "l"(c));
    return d;
}
__device__ __forceinline__ void unpack2(unsigned long long v, float& lo, float& hi) {
    asm("mov.b64 {%0, %1}, %2;" : "=f"(lo), "=f"(hi) : "l"(v));
}
#define CP_ASYNC16(dst_u32, src_ptr) \
    asm volatile("cp.async.cg.shared.global [%0], [%1], 16;" \
                 :: "r"(dst_u32), "l"(src_ptr))
#define CP_COMMIT() asm volatile("cp.async.commit_group;" ::: "memory")
#define CP_WAIT(n)  asm volatile("cp.async.wait_group %0;" :: "n"(n) : "memory")

// ---------------------------------------------------------------------------
// Kernel 1: split-K skinny GEMM (identical to R11 winner).
// Warp = 12 rows x 64 tokens (2 tok/thread: lane & lane+32).
// ---------------------------------------------------------------------------
__global__ __launch_bounds__(TPB)
void moe_gemm_kernel(const float* __restrict__ x,
                     const float* __restrict__ gate_w,
                     const float* __restrict__ expert_w)
{
    __shared__ float xs[2][TM][XST];     // 20480 B
    __shared__ float ws[NROW][WSS];      // 12672 B

    const int tid   = threadIdx.x;
    const int split = blockIdx.x & (SPLITK - 1);
    const int grp   = blockIdx.x >> 3;
    const int tok0  = grp * TM;
    const int kbase = split * KSPAN;
    const int wid   = tid >> 5;
    const int lane  = tid & 31;
    const int rb    = (wid & 1) * 12;          // row base: 0 or 12
    const int tkoff = (wid >> 1) * 64 + lane;  // first token (second = +32)

    // ---- issue x chunk 0 ----
    #pragma unroll
    for (int j = 0; j < 4; j++) {
        int i = tid + j * TPB;
        int m = i >> 2;
        int f = (i & 3) << 2;
        unsigned dst = (unsigned)__cvta_generic_to_shared(&xs[0][m][f]);
        CP_ASYNC16(dst, x + (size_t)(tok0 + m) * DIN + kbase + f);
    }
    CP_COMMIT();

    // ---- load weight tile: 24 rows x 128 floats = 768 float4 ----
    #pragma unroll
    for (int j = 0; j < (NROW * KSPAN) / (4 * TPB); j++) {   // 6
        int i   = tid + j * TPB;
        int row = i >> 5;
        int f4  = (i & 31) << 2;
        const float* src = (row < NE)
            ? (gate_w + (size_t)row * DIN)
            : (expert_w + ((size_t)(((row - NE) >> 1) * DOUT + ((row - NE) & 1))) * DIN);
        float4 v = *(const float4*)(src + kbase + f4);
        *(float4*)&ws[row][f4] = v;
    }

    unsigned long long acc0[12], acc1[12];
    #pragma unroll
    for (int r = 0; r < 12; r++) { acc0[r] = 0ULL; acc1[r] = 0ULL; }

    #pragma unroll
    for (int c = 0; c < NCH; c++) {
        const int buf = c & 1;
        if (c + 1 < NCH) {
            const int nk = kbase + (c + 1) * CH;
            #pragma unroll
            for (int j = 0; j < 4; j++) {
                int i = tid + j * TPB;
                int m = i >> 2;
                int f = (i & 3) << 2;
                unsigned dst = (unsigned)__cvta_generic_to_shared(&xs[buf ^ 1][m][f]);
                CP_ASYNC16(dst, x + (size_t)(tok0 + m) * DIN + nk + f);
            }
            CP_COMMIT();
            CP_WAIT(1);
        } else {
            CP_WAIT(0);
        }
        __syncthreads();

        // ---- compute chunk: 16 k, 12 rows, 2 tokens ----
        const float* xr0 = &xs[buf][tkoff][0];
        const float* xr1 = &xs[buf][tkoff + 32][0];
        #pragma unroll
        for (int q = 0; q < 4; q++) {
            ulonglong2 xa = *(const ulonglong2*)(xr0 + q * 4);
            ulonglong2 xb = *(const ulonglong2*)(xr1 + q * 4);
            const int kk = c * CH + q * 4;
            #pragma unroll
            for (int r = 0; r < 12; r++) {
                ulonglong2 wv = *(const ulonglong2*)(&ws[rb + r][kk]);  // broadcast
                acc0[r] = fma2(xa.x, wv.x, acc0[r]);
                acc0[r] = fma2(xa.y, wv.y, acc0[r]);
                acc1[r] = fma2(xb.x, wv.x, acc1[r]);
                acc1[r] = fma2(xb.y, wv.y, acc1[r]);
            }
        }
        __syncthreads();
    }

    // ---- write partials, coalesced: [split][row][token] ----
    const int token = tok0 + tkoff;
    #pragma unroll
    for (int r = 0; r < 12; r++) {
        float lo, hi;
        float* dst = g_scratch + ((size_t)(split * NROW + rb + r)) * BTOK + token;
        unpack2(acc0[r], lo, hi);
        dst[0]  = lo + hi;
        unpack2(acc1[r], lo, hi);
        dst[32] = lo + hi;
    }
}

// ---------------------------------------------------------------------------
// Kernel 2: many small epilogue blocks — 4 tokens/block, grid 2048.
// ---------------------------------------------------------------------------
#define ETOK 4
#define ETH  128
#define PST  25

__global__ __launch_bounds__(ETH)
void moe_epilogue_kernel(const float* __restrict__ gate_b,
                         const float* __restrict__ ebias,
                         const float* __restrict__ expert_b,
                         float* __restrict__ out,
                         float* __restrict__ idx_out)
{
    __shared__ float Pfin[ETOK][PST];
    __shared__ float wtok[ETOK];

    const int tid  = threadIdx.x;
    const int tok0 = blockIdx.x * ETOK;

    // ---- reduce: cell = (token, row); 96 cells, 8 split-loads each ----
    if (tid < ETOK * NROW) {
        const int token = tid & (ETOK - 1);
        const int row   = tid >> 2;
        const float* src = g_scratch + (size_t)row * BTOK + tok0 + token;
        float s = 0.f;
        #pragma unroll
        for (int sp = 0; sp < SPLITK; sp++)
            s += src[(size_t)(sp * NROW) * BTOK];   // 8 independent loads
        Pfin[token][row] = s;
    }
    __syncthreads();

    // ---- gating (threads 0..3) ----
    if (tid < ETOK) {
        const float* Pm = &Pfin[tid][0];
        float l[NE];
        #pragma unroll
        for (int e = 0; e < NE; e++)
            l[e] = Pm[e] + gate_b[e] + ebias[e];

        int e0 = 0; float b0 = l[0];
        #pragma unroll
        for (int e = 1; e < NE; e++)
            if (l[e] > b0) { b0 = l[e]; e0 = e; }
        int e1 = -1; float b1 = -INFINITY;
        #pragma unroll
        for (int e = 0; e < NE; e++) {
            if (e == e0) continue;
            if (l[e] > b1) { b1 = l[e]; e1 = e; }
        }

        float p0 = 1.f / (1.f + expf(-b0));
        float p1 = 1.f / (1.f + expf(-b1));
        float inv = 1.f / (p0 + p1);

        float v0 = Pm[NE + e0 * 2 + 0] + expert_b[(size_t)e0 * DOUT + 0];
        float v1 = Pm[NE + e1 * 2 + 1] + expert_b[(size_t)e1 * DOUT + 1];
        wtok[tid] = (v0 * p0 + v1 * p1) * inv;

        if (idx_out) {
            idx_out[(size_t)(tok0 + tid) * 2 + 0] = (float)e0;
            idx_out[(size_t)(tok0 + tid) * 2 + 1] = (float)e1;
        }
    }
    __syncthreads();

    // ---- broadcast write: 4 tokens x 1024 floats; 8 STG.128 per thread ----
    const int fo = tid << 2;             // 0..508
    #pragma unroll
    for (int m = 0; m < ETOK; m++) {
        float v = wtok[m];
        float4 v4 = make_float4(v, v, v, v);
        float* base = out + (size_t)(tok0 + m) * DOUT;
        *(float4*)(base + fo) = v4;
        *(float4*)(base + 512 + fo) = v4;
    }
}

extern "C" void kernel_launch(void* const* d_in, const int* in_sizes, int n_in,
                              void* d_out, int out_size)
{
    const float* x        = (const float*)d_in[0];
    const float* gate_w   = (const float*)d_in[1];
    const float* gate_b   = (const float*)d_in[2];
    const float* ebias    = (const float*)d_in[3];
    const float* expert_w = (const float*)d_in[4];
    const float* expert_b = (const float*)d_in[5];
    float* out = (float*)d_out;

    float* idx_out = nullptr;
    long long base = (long long)BTOK * DOUT;
    if ((long long)out_size >= base + (long long)BTOK * 2)
        idx_out = out + base;

    moe_gemm_kernel<<<(BTOK / TM) * SPLITK, TPB>>>(x, gate_w, expert_w);
    moe_epilogue_kernel<<<BTOK / ETOK, ETH>>>(gate_b, ebias, expert_b,
                                              out, idx_out);
}

// round 13
// speedup vs baseline: 1.9118x; 1.0026x over previous
#include <cuda_runtime.h>
#include <math.h>

// Problem constants (B=4, S=2048, D_IN=1024, D_OUT=1024, E=8, K=2)
#define BTOK    8192
#define DIN     1024
#define DOUT    1024
#define NE      8
#define NROW    24          // 8 gate rows + 16 expert rows (e, o in {0,1})
#define SPLITK  8
#define KSPAN   (DIN / SPLITK)   // 128 k per block
#define CH      16          // k per pipelined chunk
#define NCH     (KSPAN / CH)     // 8
#define TM      128         // tokens per block
#define TPB     128
#define XST     20          // xs token-row stride (floats); 80B rows, 16B-aligned
#define WSS     132         // ws row stride

// Partials: scratch[(split*NROW + row)*BTOK + token]
__device__ float g_scratch[SPLITK * NROW * BTOK];   // 6.3 MB

__device__ __forceinline__ unsigned long long fma2(unsigned long long a,
                                                   unsigned long long b,
                                                   unsigned long long c) {
    unsigned long long d;
    asm("fma.rn.f32x2 %0, %1, %2, %3;" : "=l"(d) : "l"(a), "l"(b), "l"(c));
    return d;
}
__device__ __forceinline__ void unpack2(unsigned long long v, float& lo, float& hi) {
    asm("mov.b64 {%0, %1}, %2;" : "=f"(lo), "=f"(hi) : "l"(v));
}
#define CP_ASYNC16(dst_u32, src_ptr) \
    asm volatile("cp.async.cg.shared.global [%0], [%1], 16;" \
                 :: "r"(dst_u32), "l"(src_ptr))
#define CP_COMMIT() asm volatile("cp.async.commit_group;" ::: "memory")
#define CP_WAIT(n)  asm volatile("cp.async.wait_group %0;" :: "n"(n) : "memory")

// ---------------------------------------------------------------------------
// Kernel 1: split-K skinny GEMM. Warp = 12 rows x 64 tokens (2 tok/thread).
// 3-stage cp.async pipeline (2 chunks in flight), one sync per chunk.
// ---------------------------------------------------------------------------
__global__ __launch_bounds__(TPB, 5)
void moe_gemm_kernel(const float* __restrict__ x,
                     const float* __restrict__ gate_w,
                     const float* __restrict__ expert_w)
{
    __shared__ float xs[3][TM][XST];     // 30720 B
    __shared__ float ws[NROW][WSS];      // 12672 B

    const int tid   = threadIdx.x;
    const int split = blockIdx.x & (SPLITK - 1);
    const int grp   = blockIdx.x >> 3;
    const int tok0  = grp * TM;
    const int kbase = split * KSPAN;
    const int wid   = tid >> 5;
    const int lane  = tid & 31;
    const int rb    = (wid & 1) * 12;          // row base: 0 or 12
    const int tkoff = (wid >> 1) * 64 + lane;  // first token (second = +32)

    // per-thread x-staging coords (fixed across chunks)
    const int xm = tid >> 2;            // token row handled by this thread... (4 thr/row? no)
    // NOTE: 128 threads stage 128 tokens x 16 floats = 512 float4; each thread
    // does 4 float4: thread i covers token i>>2? -> need i in [0,512). Use loop.

    // ---- prologue: issue chunks 0 and 1 ----
    #pragma unroll
    for (int pc = 0; pc < 2; pc++) {
        const int k0 = kbase + pc * CH;
        #pragma unroll
        for (int j = 0; j < 4; j++) {
            int i = tid + j * TPB;
            int m = i >> 2;
            int f = (i & 3) << 2;
            unsigned dst = (unsigned)__cvta_generic_to_shared(&xs[pc][m][f]);
            CP_ASYNC16(dst, x + (size_t)(tok0 + m) * DIN + k0 + f);
        }
        CP_COMMIT();
    }
    (void)xm;

    // ---- load weight tile: 24 rows x 128 floats = 768 float4 ----
    #pragma unroll
    for (int j = 0; j < (NROW * KSPAN) / (4 * TPB); j++) {   // 6
        int i   = tid + j * TPB;
        int row = i >> 5;
        int f4  = (i & 31) << 2;
        const float* src = (row < NE)
            ? (gate_w + (size_t)row * DIN)
            : (expert_w + ((size_t)(((row - NE) >> 1) * DOUT + ((row - NE) & 1))) * DIN);
        float4 v = *(const float4*)(src + kbase + f4);
        *(float4*)&ws[row][f4] = v;
    }

    unsigned long long acc0[12], acc1[12];
    #pragma unroll
    for (int r = 0; r < 12; r++) { acc0[r] = 0ULL; acc1[r] = 0ULL; }

    #pragma unroll
    for (int c = 0; c < NCH; c++) {
        const int buf = c % 3;
        if (c == NCH - 1) { CP_WAIT(0); } else { CP_WAIT(1); }
        __syncthreads();          // chunk c visible to all; buf (c+2)%3 free

        if (c + 2 < NCH) {
            const int nk = kbase + (c + 2) * CH;
            const int nb = (c + 2) % 3;
            #pragma unroll
            for (int j = 0; j < 4; j++) {
                int i = tid + j * TPB;
                int m = i >> 2;
                int f = (i & 3) << 2;
                unsigned dst = (unsigned)__cvta_generic_to_shared(&xs[nb][m][f]);
                CP_ASYNC16(dst, x + (size_t)(tok0 + m) * DIN + nk + f);
            }
            CP_COMMIT();
        }

        // ---- compute chunk: 16 k, 12 rows, 2 tokens ----
        const float* xr0 = &xs[buf][tkoff][0];
        const float* xr1 = &xs[buf][tkoff + 32][0];
        #pragma unroll
        for (int q = 0; q < 4; q++) {
            ulonglong2 xa = *(const ulonglong2*)(xr0 + q * 4);
            ulonglong2 xb = *(const ulonglong2*)(xr1 + q * 4);
            const int kk = c * CH + q * 4;
            #pragma unroll
            for (int r = 0; r < 12; r++) {
                ulonglong2 wv = *(const ulonglong2*)(&ws[rb + r][kk]);  // broadcast
                acc0[r] = fma2(xa.x, wv.x, acc0[r]);
                acc0[r] = fma2(xa.y, wv.y, acc0[r]);
                acc1[r] = fma2(xb.x, wv.x, acc1[r]);
                acc1[r] = fma2(xb.y, wv.y, acc1[r]);
            }
        }
    }

    // ---- write partials, coalesced: [split][row][token] ----
    const int token = tok0 + tkoff;
    #pragma unroll
    for (int r = 0; r < 12; r++) {
        float lo, hi;
        float* dst = g_scratch + ((size_t)(split * NROW + rb + r)) * BTOK + token;
        unpack2(acc0[r], lo, hi);
        dst[0]  = lo + hi;
        unpack2(acc1[r], lo, hi);
        dst[32] = lo + hi;
    }
}

// ---------------------------------------------------------------------------
// Kernel 2: many small epilogue blocks — 4 tokens/block, grid 2048 (R12).
// ---------------------------------------------------------------------------
#define ETOK 4
#define ETH  128
#define PST  25

__global__ __launch_bounds__(ETH)
void moe_epilogue_kernel(const float* __restrict__ gate_b,
                         const float* __restrict__ ebias,
                         const float* __restrict__ expert_b,
                         float* __restrict__ out,
                         float* __restrict__ idx_out)
{
    __shared__ float Pfin[ETOK][PST];
    __shared__ float wtok[ETOK];

    const int tid  = threadIdx.x;
    const int tok0 = blockIdx.x * ETOK;

    // ---- reduce: cell = (token, row); 96 cells, 8 split-loads each ----
    if (tid < ETOK * NROW) {
        const int token = tid & (ETOK - 1);
        const int row   = tid >> 2;
        const float* src = g_scratch + (size_t)row * BTOK + tok0 + token;
        float s = 0.f;
        #pragma unroll
        for (int sp = 0; sp < SPLITK; sp++)
            s += src[(size_t)(sp * NROW) * BTOK];   // 8 independent loads
        Pfin[token][row] = s;
    }
    __syncthreads();

    // ---- gating (threads 0..3) ----
    if (tid < ETOK) {
        const float* Pm = &Pfin[tid][0];
        float l[NE];
        #pragma unroll
        for (int e = 0; e < NE; e++)
            l[e] = Pm[e] + gate_b[e] + ebias[e];

        int e0 = 0; float b0 = l[0];
        #pragma unroll
        for (int e = 1; e < NE; e++)
            if (l[e] > b0) { b0 = l[e]; e0 = e; }
        int e1 = -1; float b1 = -INFINITY;
        #pragma unroll
        for (int e = 0; e < NE; e++) {
            if (e == e0) continue;
            if (l[e] > b1) { b1 = l[e]; e1 = e; }
        }

        float p0 = 1.f / (1.f + expf(-b0));
        float p1 = 1.f / (1.f + expf(-b1));
        float inv = 1.f / (p0 + p1);

        float v0 = Pm[NE + e0 * 2 + 0] + expert_b[(size_t)e0 * DOUT + 0];
        float v1 = Pm[NE + e1 * 2 + 1] + expert_b[(size_t)e1 * DOUT + 1];
        wtok[tid] = (v0 * p0 + v1 * p1) * inv;

        if (idx_out) {
            idx_out[(size_t)(tok0 + tid) * 2 + 0] = (float)e0;
            idx_out[(size_t)(tok0 + tid) * 2 + 1] = (float)e1;
        }
    }
    __syncthreads();

    // ---- broadcast write: 4 tokens x 1024 floats; 8 STG.128 per thread ----
    const int fo = tid << 2;             // 0..508
    #pragma unroll
    for (int m = 0; m < ETOK; m++) {
        float v = wtok[m];
        float4 v4 = make_float4(v, v, v, v);
        float* base = out + (size_t)(tok0 + m) * DOUT;
        *(float4*)(base + fo) = v4;
        *(float4*)(base + 512 + fo) = v4;
    }
}

extern "C" void kernel_launch(void* const* d_in, const int* in_sizes, int n_in,
                              void* d_out, int out_size)
{
    const float* x        = (const float*)d_in[0];
    const float* gate_w   = (const float*)d_in[1];
    const float* gate_b   = (const float*)d_in[2];
    const float* ebias    = (const float*)d_in[3];
    const float* expert_w = (const float*)d_in[4];
    const float* expert_b = (const float*)d_in[5];
    float* out = (float*)d_out;

    float* idx_out = nullptr;
    long long base = (long long)BTOK * DOUT;
    if ((long long)out_size >= base + (long long)BTOK * 2)
        idx_out = out + base;

    // allow max smem carveout so 5 blocks/SM fit
    cudaFuncSetAttribute(moe_gemm_kernel,
                         cudaFuncAttributePreferredSharedMemoryCarveout, 100);

    moe_gemm_kernel<<<(BTOK / TM) * SPLITK, TPB>>>(x, gate_w, expert_w);
    moe_epilogue_kernel<<<BTOK / ETOK, ETH>>>(gate_b, ebias, expert_b,
                                              out, idx_out);
}

// round 14
// speedup vs baseline: 2.0536x; 1.0742x over previous
#include <cuda_runtime.h>
#include <math.h>

// Problem constants (B=4, S=2048, D_IN=1024, D_OUT=1024, E=8, K=2)
#define BTOK    8192
#define DIN     1024
#define DOUT    1024
#define NE      8
#define SPLITK  8
#define KSPAN   (DIN / SPLITK)   // 128 k per split
#define CH      16               // k per pipelined chunk
#define NCH     (KSPAN / CH)     // 8
#define TM      256              // tokens per K1 block (4 warps x 64 tokens)
#define TPB     128
#define XST     20               // xs token-row stride (floats); 80B rows

// Gate partials: g_gate[token*64 + split*8 + row]  (2 MB)
__device__ float g_gate[BTOK * SPLITK * NE];

__device__ __forceinline__ unsigned long long fma2(unsigned long long a,
                                                   unsigned long long b,
                                                   unsigned long long c) {
    unsigned long long d;
    asm("fma.rn.f32x2 %0, %1, %2, %3;" : "=l"(d) : "l"(a), "l"(b), "l"(c));
    return d;
}
__device__ __forceinline__ void unpack2(unsigned long long v, float& lo, float& hi) {
    asm("mov.b64 {%0, %1}, %2;" : "=f"(lo), "=f"(hi) : "l"(v));
}
#define CP_ASYNC16(dst_u32, src_ptr) \
    asm volatile("cp.async.cg.shared.global [%0], [%1], 16;" \
                 :: "r"(dst_u32), "l"(src_ptr))
#define CP_COMMIT() asm volatile("cp.async.commit_group;" ::: "memory")
#define CP_WAIT(n)  asm volatile("cp.async.wait_group %0;" :: "n"(n) : "memory")

// ---------------------------------------------------------------------------
// Kernel 1: gate GEMM only (8 rows). Split-K 8, cp.async double-buffered x,
// warp = 8 rows x 64 tokens (2 tok/thread: lane & lane+32), FFMA2.
// ---------------------------------------------------------------------------
__global__ __launch_bounds__(TPB)
void gate_gemm_kernel(const float* __restrict__ x,
                      const float* __restrict__ gate_w)
{
    __shared__ float xs[2][TM][XST];     // 40960 B
    __shared__ float ws[NE][132];        // 4224 B

    const int tid   = threadIdx.x;
    const int split = blockIdx.x & (SPLITK - 1);
    const int grp   = blockIdx.x >> 3;
    const int tok0  = grp * TM;
    const int kbase = split * KSPAN;
    const int wid   = tid >> 5;
    const int lane  = tid & 31;
    const int tkoff = wid * 64 + lane;      // tokens tkoff, tkoff+32 (in block)

    // ---- issue x chunk 0: 256 tok x 16 k = 1024 float4, 8/thread ----
    #pragma unroll
    for (int j = 0; j < 8; j++) {
        int i = tid + j * TPB;
        int m = i >> 2;
        int f = (i & 3) << 2;
        unsigned dst = (unsigned)__cvta_generic_to_shared(&xs[0][m][f]);
        CP_ASYNC16(dst, x + (size_t)(tok0 + m) * DIN + kbase + f);
    }
    CP_COMMIT();

    // ---- gate weights: 8 rows x 128 floats = 256 float4, 2/thread ----
    #pragma unroll
    for (int j = 0; j < 2; j++) {
        int i   = tid + j * TPB;
        int row = i >> 5;
        int f4  = (i & 31) << 2;
        float4 v = *(const float4*)(gate_w + (size_t)row * DIN + kbase + f4);
        *(float4*)&ws[row][f4] = v;
    }

    unsigned long long acc0[NE], acc1[NE];
    #pragma unroll
    for (int r = 0; r < NE; r++) { acc0[r] = 0ULL; acc1[r] = 0ULL; }

    #pragma unroll
    for (int c = 0; c < NCH; c++) {
        const int buf = c & 1;
        if (c + 1 < NCH) {
            const int nk = kbase + (c + 1) * CH;
            #pragma unroll
            for (int j = 0; j < 8; j++) {
                int i = tid + j * TPB;
                int m = i >> 2;
                int f = (i & 3) << 2;
                unsigned dst = (unsigned)__cvta_generic_to_shared(&xs[buf ^ 1][m][f]);
                CP_ASYNC16(dst, x + (size_t)(tok0 + m) * DIN + nk + f);
            }
            CP_COMMIT();
            CP_WAIT(1);
        } else {
            CP_WAIT(0);
        }
        __syncthreads();

        const float* xr0 = &xs[buf][tkoff][0];
        const float* xr1 = &xs[buf][tkoff + 32][0];
        #pragma unroll
        for (int q = 0; q < 4; q++) {
            ulonglong2 xa = *(const ulonglong2*)(xr0 + q * 4);
            ulonglong2 xb = *(const ulonglong2*)(xr1 + q * 4);
            const int kk = c * CH + q * 4;
            #pragma unroll
            for (int r = 0; r < NE; r++) {
                ulonglong2 wv = *(const ulonglong2*)(&ws[r][kk]);   // broadcast
                acc0[r] = fma2(xa.x, wv.x, acc0[r]);
                acc0[r] = fma2(xa.y, wv.y, acc0[r]);
                acc1[r] = fma2(xb.x, wv.x, acc1[r]);
                acc1[r] = fma2(xb.y, wv.y, acc1[r]);
            }
        }
        __syncthreads();
    }

    // ---- store gate partials: g_gate[token*64 + split*8 + row] ----
    {
        float s[NE];
        #pragma unroll
        for (int r = 0; r < NE; r++) {
            float lo, hi; unpack2(acc0[r], lo, hi); s[r] = lo + hi;
        }
        float4* dst = (float4*)(g_gate + (size_t)(tok0 + tkoff) * 64 + split * 8);
        dst[0] = make_float4(s[0], s[1], s[2], s[3]);
        dst[1] = make_float4(s[4], s[5], s[6], s[7]);
    }
    {
        float s[NE];
        #pragma unroll
        for (int r = 0; r < NE; r++) {
            float lo, hi; unpack2(acc1[r], lo, hi); s[r] = lo + hi;
        }
        float4* dst = (float4*)(g_gate + (size_t)(tok0 + tkoff + 32) * 64 + split * 8);
        dst[0] = make_float4(s[0], s[1], s[2], s[3]);
        dst[1] = make_float4(s[4], s[5], s[6], s[7]);
    }
}

// ---------------------------------------------------------------------------
// Kernel 2: warp-per-token — gate reduce + top-2 + 2 expert dots + write.
// ---------------------------------------------------------------------------
__global__ __launch_bounds__(256)
void moe_out_kernel(const float* __restrict__ x,
                    const float* __restrict__ gate_b,
                    const float* __restrict__ ebias,
                    const float* __restrict__ expert_w,
                    const float* __restrict__ expert_b,
                    float* __restrict__ out,
                    float* __restrict__ idx_out)
{
    __shared__ float gbias[NE];
    const int tid  = threadIdx.x;
    const int wid  = tid >> 5;
    const int lane = tid & 31;

    if (tid < NE) gbias[tid] = gate_b[tid] + ebias[tid];
    __syncthreads();

    const int gw = blockIdx.x * 8 + wid;      // global warp id: 0..2047

    #pragma unroll
    for (int t = 0; t < 4; t++) {
        const int token = gw * 4 + t;

        // ---- gate reduce: 64 floats, lane loads float2, xor-reduce splits ----
        float2 g2 = *(const float2*)(g_gate + (size_t)token * 64 + lane * 2);
        #pragma unroll
        for (int off = 4; off <= 16; off <<= 1) {
            g2.x += __shfl_xor_sync(0xFFFFFFFFu, g2.x, off);
            g2.y += __shfl_xor_sync(0xFFFFFFFFu, g2.y, off);
        }
        // lane l holds totals for rows (2*(l&3), 2*(l&3)+1)
        float logit[NE];
        #pragma unroll
        for (int i = 0; i < 4; i++) {
            float lx = __shfl_sync(0xFFFFFFFFu, g2.x, i);
            float ly = __shfl_sync(0xFFFFFFFFu, g2.y, i);
            logit[2 * i]     = lx + gbias[2 * i];
            logit[2 * i + 1] = ly + gbias[2 * i + 1];
        }

        // ---- top-2, first-occurrence tie-break (warp-uniform) ----
        int e0 = 0; float b0 = logit[0];
        #pragma unroll
        for (int e = 1; e < NE; e++)
            if (logit[e] > b0) { b0 = logit[e]; e0 = e; }
        int e1 = -1; float b1 = -INFINITY;
        #pragma unroll
        for (int e = 0; e < NE; e++) {
            if (e == e0) continue;
            if (logit[e] > b1) { b1 = logit[e]; e1 = e; }
        }

        // ---- two expert dots: lane-parallel over K, coalesced float4 ----
        const float4* xv = (const float4*)(x + (size_t)token * DIN);
        const float4* w0 = (const float4*)(expert_w + ((size_t)e0 * DOUT + 0) * DIN);
        const float4* w1 = (const float4*)(expert_w + ((size_t)e1 * DOUT + 1) * DIN);
        float a0 = 0.f, a1 = 0.f;
        #pragma unroll
        for (int j = 0; j < 8; j++) {
            float4 xx = xv[j * 32 + lane];
            float4 u0 = w0[j * 32 + lane];
            float4 u1 = w1[j * 32 + lane];
            a0 = fmaf(xx.x, u0.x, a0); a0 = fmaf(xx.y, u0.y, a0);
            a0 = fmaf(xx.z, u0.z, a0); a0 = fmaf(xx.w, u0.w, a0);
            a1 = fmaf(xx.x, u1.x, a1); a1 = fmaf(xx.y, u1.y, a1);
            a1 = fmaf(xx.z, u1.z, a1); a1 = fmaf(xx.w, u1.w, a1);
        }
        #pragma unroll
        for (int off = 16; off > 0; off >>= 1) {
            a0 += __shfl_xor_sync(0xFFFFFFFFu, a0, off);
            a1 += __shfl_xor_sync(0xFFFFFFFFu, a1, off);
        }

        float v0 = a0 + expert_b[(size_t)e0 * DOUT + 0];
        float v1 = a1 + expert_b[(size_t)e1 * DOUT + 1];
        float p0 = 1.f / (1.f + expf(-b0));
        float p1 = 1.f / (1.f + expf(-b1));
        float wv = (v0 * p0 + v1 * p1) / (p0 + p1);

        if (idx_out && lane == 0) {
            idx_out[(size_t)token * 2 + 0] = (float)e0;
            idx_out[(size_t)token * 2 + 1] = (float)e1;
        }

        // ---- broadcast write: 1024 floats, 8 STG.128 per lane ----
        float4 v4 = make_float4(wv, wv, wv, wv);
        float4* orow = (float4*)(out + (size_t)token * DOUT);
        #pragma unroll
        for (int j = 0; j < 8; j++)
            orow[j * 32 + lane] = v4;
    }
}

extern "C" void kernel_launch(void* const* d_in, const int* in_sizes, int n_in,
                              void* d_out, int out_size)
{
    const float* x        = (const float*)d_in[0];
    const float* gate_w   = (const float*)d_in[1];
    const float* gate_b   = (const float*)d_in[2];
    const float* ebias    = (const float*)d_in[3];
    const float* expert_w = (const float*)d_in[4];
    const float* expert_b = (const float*)d_in[5];
    float* out = (float*)d_out;

    float* idx_out = nullptr;
    long long base = (long long)BTOK * DOUT;
    if ((long long)out_size >= base + (long long)BTOK * 2)
        idx_out = out + base;

    gate_gemm_kernel<<<(BTOK / TM) * SPLITK, TPB>>>(x, gate_w);
    moe_out_kernel<<<BTOK / 32, 256>>>(x, gate_b, ebias, expert_w, expert_b,
                                       out, idx_out);
}